// round 3
// baseline (speedup 1.0000x reference)
#include <cuda_runtime.h>
#include <cuda_bf16.h>
#include <float.h>
#include <math.h>

#define S 2048
#define D 1024
#define NMEM 32
#define TILES 32            // S / 64 rows per block
#define PATCH 32

// ---------------- scratch (static device globals; no allocation) ----------------
__device__ float g_entropy [NMEM * S];        // per-memory row entropy
__device__ float g_entropy2[S];               // query-dummy / aggregated row entropy
__device__ float g_part    [(NMEM + 2) * TILES * D]; // partial column sums (34 slots x 32 tiles)
__device__ float g_colmean [(NMEM + 1) * D];  // 32 memory col-means + query col-mean
__device__ int   g_topidx  [NMEM * PATCH];
__device__ int   g_fidx    [PATCH];
__device__ float g_agg     [S * D];           // query + scattered patches (= aggregated * 33)
__device__ float g_emb     [(NMEM + 1) * D];
__device__ double g_norm   [NMEM + 1];

// ---------------- kernel A: row stats (sum, sumsq -> std ddof=1) + partial colsums ----
// grid = n_count * TILES blocks, 256 threads. Each warp handles 8 rows.
// esel: 0 -> g_entropy, 1 -> g_entropy2.  src==nullptr -> read g_agg.
__global__ void rowstats_kernel(const float* __restrict__ src_in, int esel, int part_base)
{
    const float* src = src_in ? src_in : g_agg;
    const int bx = blockIdx.x;
    const int tile = bx % TILES;
    const int n    = bx / TILES;
    const int t = threadIdx.x;
    const int w = t >> 5, l = t & 31;

    __shared__ float cs[8 * 1024];

    float4 colacc[8];
#pragma unroll
    for (int j = 0; j < 8; j++) colacc[j] = make_float4(0.f, 0.f, 0.f, 0.f);

    const float* base = src + (size_t)n * S * D;
    const int row0 = tile * 64 + w * 8;

    for (int k = 0; k < 8; k++) {
        const int s = row0 + k;
        const float4* rp = reinterpret_cast<const float4*>(base + (size_t)s * D);
        float s1 = 0.f, s2 = 0.f;
#pragma unroll
        for (int j = 0; j < 8; j++) {
            float4 x = rp[l + 32 * j];
            colacc[j].x += x.x; colacc[j].y += x.y; colacc[j].z += x.z; colacc[j].w += x.w;
            s1 += (x.x + x.y) + (x.z + x.w);
            s2 += (x.x * x.x + x.y * x.y) + (x.z * x.z + x.w * x.w);
        }
        // warp reduce in double for precision
        double d1 = (double)s1, d2 = (double)s2;
#pragma unroll
        for (int off = 16; off; off >>= 1) {
            d1 += __shfl_down_sync(0xffffffffu, d1, off);
            d2 += __shfl_down_sync(0xffffffffu, d2, off);
        }
        if (l == 0) {
            double var = (d2 - d1 * d1 * (1.0 / (double)D)) * (1.0 / (double)(D - 1));
            float e = (float)sqrt(var > 0.0 ? var : 0.0);
            if (esel == 0) g_entropy[(size_t)n * S + s] = e;
            else           g_entropy2[s] = e;   // n==0 for this path
        }
    }

    // deterministic column-sum combine across the 8 warps
#pragma unroll
    for (int j = 0; j < 8; j++)
        reinterpret_cast<float4*>(&cs[w * 1024 + 4 * (l + 32 * j)])[0] = colacc[j];
    __syncthreads();
#pragma unroll
    for (int g = 0; g < 4; g++) {
        const int d = t + 256 * g;
        float ssum = 0.f;
#pragma unroll
        for (int w2 = 0; w2 < 8; w2++) ssum += cs[w2 * 1024 + d];
        g_part[(size_t)(part_base + bx) * D + d] = ssum;
    }
}

// ---------------- kernel B: reduce partial colsums -> colmean (33 blocks) ----------
__global__ void colmean_kernel()
{
    const int n = blockIdx.x, t = threadIdx.x;
#pragma unroll
    for (int g = 0; g < 4; g++) {
        const int d = t + 256 * g;
        float s = 0.f;
#pragma unroll 8
        for (int p = 0; p < TILES; p++) s += g_part[(size_t)(n * TILES + p) * D + d];
        g_colmean[n * D + d] = s * (1.0f / (float)S);
    }
}

// ---------------- kernel C: top-32 of 2048 entropies (1 warp/block) ----------------
// esel: 0 -> g_entropy (block n), 1 -> g_entropy2 (single block). osel: 0 -> g_topidx, 1 -> g_fidx.
__global__ void topk_kernel(int esel, int osel)
{
    const int n = blockIdx.x;
    const int l = threadIdx.x;
    __shared__ float sv[S];
    const float* e = (esel == 0) ? (g_entropy + (size_t)n * S) : g_entropy2;
    for (int k = 0; k < S / 32; k++) sv[l + 32 * k] = e[l + 32 * k];
    __syncwarp();
    for (int it = 0; it < PATCH; it++) {
        float bv = -FLT_MAX; int bi = 1 << 30;
        for (int k = 0; k < S / 32; k++) {
            const int idx = l + 32 * k;
            const float v = sv[idx];
            if (v > bv || (v == bv && idx < bi)) { bv = v; bi = idx; }
        }
#pragma unroll
        for (int off = 16; off; off >>= 1) {
            float ov = __shfl_down_sync(0xffffffffu, bv, off);
            int   oi = __shfl_down_sync(0xffffffffu, bi, off);
            if (ov > bv || (ov == bv && oi < bi)) { bv = ov; bi = oi; }
        }
        bi = __shfl_sync(0xffffffffu, bi, 0);
        if (l == 0) {
            if (osel == 0) g_topidx[n * PATCH + it] = bi;
            else           g_fidx[it] = bi;
        }
        if (l == (bi & 31)) sv[bi] = -FLT_MAX;
        __syncwarp();
    }
}

// ---------------- kernel D: agg = query copy, out[0..S*D) = 0 -----------------------
__global__ void init_agg_kernel(const float* __restrict__ q, float* __restrict__ out)
{
    const int i = blockIdx.x * blockDim.x + threadIdx.x;  // float4 index, S*D/4 total
    float4 v = reinterpret_cast<const float4*>(q)[i];
    reinterpret_cast<float4*>(g_agg)[i] = v;
    reinterpret_cast<float4*>(out)[i] = make_float4(0.f, 0.f, 0.f, 0.f);
}

__device__ __forceinline__ float trunc_clip(float x)
{
    return truncf(fminf(fmaxf(x, -128.f), 127.f));
}

// ---------------- kernel E: scatter truncated patches into agg ----------------------
// grid = NMEM*PATCH blocks, 256 threads (one float4 each). Integer-valued fp adds -> exact.
__global__ void scatter_kernel(const float* __restrict__ mem)
{
    const int b = blockIdx.x;
    const int n = b >> 5, j = b & 31;
    const int row = g_topidx[n * PATCH + j];
    const int t = threadIdx.x;
    float4 x = reinterpret_cast<const float4*>(mem + ((size_t)n * S + row) * D)[t];
    float* dst = g_agg + (size_t)row * D + 4 * t;
    atomicAdd(dst + 0, trunc_clip(x.x));
    atomicAdd(dst + 1, trunc_clip(x.y));
    atomicAdd(dst + 2, trunc_clip(x.z));
    atomicAdd(dst + 3, trunc_clip(x.w));
}

// ---------------- kernel H: write recon rows -----------------------------------------
__global__ void recon_kernel(float* __restrict__ out)
{
    const int row = g_fidx[blockIdx.x];
    const int t = threadIdx.x;
    float4 x = reinterpret_cast<float4*>(g_agg + (size_t)row * D)[t];
    const float inv = 1.0f / 33.0f;
    float4 r;
    r.x = trunc_clip(x.x * inv);
    r.y = trunc_clip(x.y * inv);
    r.z = trunc_clip(x.z * inv);
    r.w = trunc_clip(x.w * inv);
    reinterpret_cast<float4*>(out + (size_t)row * D)[t] = r;
}

// ---------------- kernel M: meta MLP (33 blocks x 128 threads) -----------------------
__global__ void mlp_kernel(const float* __restrict__ surprise,
                           const float* __restrict__ W1, const float* __restrict__ b1,
                           const float* __restrict__ W2, const float* __restrict__ b2)
{
    const int n = blockIdx.x;       // 0..31 memories, 32 = query
    const int t = threadIdx.x;      // 128
    __shared__ float feat[1028];
    __shared__ float hsm[128];
    __shared__ double red[128];

#pragma unroll
    for (int g = 0; g < 8; g++) feat[t + 128 * g] = g_colmean[n * D + t + 128 * g];
    if (t == 0) {
        feat[1024] = (n < NMEM) ? surprise[n] : 0.f;
        feat[1025] = 0.f; feat[1026] = 0.f;
    }
    __syncthreads();

    float acc = b1[t];
    for (int i = 0; i < 1027; i++) acc = fmaf(feat[i], W1[i * 128 + t], acc);
    hsm[t] = acc > 0.f ? acc : 0.f;
    __syncthreads();

    double nrm = 0.0;
#pragma unroll
    for (int g = 0; g < 8; g++) {
        const int d = t + 128 * g;
        float e = b2[d];
#pragma unroll 8
        for (int k = 0; k < 128; k++) e = fmaf(hsm[k], W2[k * D + d], e);
        g_emb[n * D + d] = e;
        nrm += (double)e * (double)e;
    }
    red[t] = nrm;
    __syncthreads();
#pragma unroll
    for (int off = 64; off; off >>= 1) { if (t < off) red[t] += red[t + off]; __syncthreads(); }
    if (t == 0) g_norm[n] = sqrt(red[0]);
}

// ---------------- kernel S: cosine sims * priority + full descending argsort ---------
__global__ void sims_kernel(const float* __restrict__ pm, float* __restrict__ out)
{
    const int l = threadIdx.x;   // 32
    __shared__ float ss[NMEM];
    double dot = 0.0;
    for (int d = 0; d < D; d++)
        dot += (double)g_emb[l * D + d] * (double)g_emb[NMEM * D + d];
    const double nn = g_norm[l], nq = g_norm[NMEM];
    const double sim = dot / (fmax(nn, 1e-8) * fmax(nq, 1e-8)) * (double)pm[l];
    const float simf = (float)sim;
    out[(size_t)S * D + l] = simf;
    ss[l] = simf;
    __syncwarp();
    if (l == 0) {
        bool used[NMEM];
        for (int i = 0; i < NMEM; i++) used[i] = false;
        for (int r = 0; r < NMEM; r++) {
            float bv = -FLT_MAX; int bi = 0;
            for (int i = 0; i < NMEM; i++)
                if (!used[i] && ss[i] > bv) { bv = ss[i]; bi = i; }
            used[bi] = true;
            out[(size_t)S * D + NMEM + r] = (float)bi;
        }
    }
}

// ---------------- launch ------------------------------------------------------------
extern "C" void kernel_launch(void* const* d_in, const int* in_sizes, int n_in,
                              void* d_out, int out_size)
{
    const float* query    = (const float*)d_in[0];
    const float* memories = (const float*)d_in[1];
    const float* surprise = (const float*)d_in[2];
    const float* pm       = (const float*)d_in[3];
    const float* W1       = (const float*)d_in[4];
    const float* b1       = (const float*)d_in[5];
    const float* W2       = (const float*)d_in[6];
    const float* b2       = (const float*)d_in[7];
    float* out = (float*)d_out;

    // 1) per-memory row entropy + partial colsums (the one big 268MB pass)
    rowstats_kernel<<<NMEM * TILES, 256>>>(memories, /*esel=*/0, /*part_base=*/0);
    // 2) query colsums (entropy side goes to g_entropy2 as scratch, overwritten later)
    rowstats_kernel<<<TILES, 256>>>(query, /*esel=*/1, /*part_base=*/NMEM * TILES);
    // 3) reduce colsums -> colmeans (memories + query)
    colmean_kernel<<<NMEM + 1, 256>>>();
    // 4) per-memory top-32 entropy rows
    topk_kernel<<<NMEM, 32>>>(/*esel=*/0, /*osel=*/0);
    // 5) agg = query, zero recon region of out
    init_agg_kernel<<<(S * D / 4) / 256, 256>>>(query, out);
    // 6) scatter truncated patches into agg (exact integer fp adds)
    scatter_kernel<<<NMEM * PATCH, 256>>>(memories);
    // 7) row entropy of aggregated (scale-invariant ranking; src=nullptr -> g_agg)
    rowstats_kernel<<<TILES, 256>>>(nullptr, /*esel=*/1, /*part_base=*/(NMEM + 1) * TILES);
    // 8) final top-32 rows
    topk_kernel<<<1, 32>>>(/*esel=*/1, /*osel=*/1);
    // 9) write recon rows (trunc(clip(agg/33)))
    recon_kernel<<<PATCH, 256>>>(out);
    // 10) meta-learner embeddings + norms
    mlp_kernel<<<NMEM + 1, 128>>>(surprise, W1, b1, W2, b2);
    // 11) sims + top_idx
    sims_kernel<<<1, 32>>>(pm, out);
}

// round 4
// speedup vs baseline: 1.3636x; 1.3636x over previous
#include <cuda_runtime.h>
#include <cuda_bf16.h>
#include <float.h>
#include <math.h>

#define S 2048
#define D 1024
#define NMEM 32
#define TILES 32            // S / 64 rows per block
#define PATCH 32

// ---------------- scratch (static device globals; no allocation) ----------------
__device__ float g_entropy [NMEM * S];        // per-memory row entropy
__device__ float g_entropy2[S];               // aggregated row entropy
__device__ float g_part    [(NMEM + 2) * TILES * D]; // partial column sums
__device__ float g_colmean [(NMEM + 1) * D];  // 32 memory col-means + query col-mean
__device__ int   g_topidx  [NMEM * PATCH];
__device__ int   g_fidx    [PATCH];
__device__ float g_agg     [S * D];           // query + scattered patches (= aggregated * 33)
__device__ float g_emb     [(NMEM + 1) * D];
__device__ double g_norm   [NMEM + 1];

// ---------------- cp.async helpers --------------------------------------------------
__device__ __forceinline__ void cp_async16(float* sdst, const float* gsrc)
{
    unsigned sa = (unsigned)__cvta_generic_to_shared(sdst);
    asm volatile("cp.async.cg.shared.global [%0], [%1], 16;" :: "r"(sa), "l"(gsrc) : "memory");
}
__device__ __forceinline__ void cp_commit() { asm volatile("cp.async.commit_group;" ::: "memory"); }

// issue one 4KB row: lane l copies 8 x 16B
__device__ __forceinline__ void issue_row(const float* g, float* slot, int l)
{
#pragma unroll
    for (int j = 0; j < 8; j++)
        cp_async16(slot + (l + 32 * j) * 4, g + (l + 32 * j) * 4);
    cp_commit();
}

// ---------------- kernel A: row stats + partial colsums, cp.async pipelined ---------
// grid = n_count * TILES blocks, 256 threads (8 warps). Warp w handles 8 rows.
// dynamic smem: ring[8 warps][2 slots][1024 floats] (64KB) + cs[8][1024] (32KB) = 96KB
__global__ void __launch_bounds__(256)
rowstats_kernel(const float* __restrict__ src_in, int esel, int part_base)
{
    extern __shared__ float sm[];
    float* ring = sm;                 // 16384 floats
    float* cs   = sm + 16384;         // 8192 floats

    const float* src = src_in ? src_in : g_agg;
    const int bx = blockIdx.x;
    const int tile = bx % TILES;
    const int n    = bx / TILES;
    const int t = threadIdx.x;
    const int w = t >> 5, l = t & 31;

    const float* base = src + (size_t)n * S * D;
    const int row0 = tile * 64 + w * 8;
    const float* rowbase = base + (size_t)row0 * D;
    float* wring = ring + w * 2048;

    float4 colacc[8];
#pragma unroll
    for (int j = 0; j < 8; j++) colacc[j] = make_float4(0.f, 0.f, 0.f, 0.f);

    // prime the 2-deep pipeline
    issue_row(rowbase + 0 * (size_t)D, wring,        l);
    issue_row(rowbase + 1 * (size_t)D, wring + 1024, l);

#pragma unroll
    for (int k = 0; k < 8; k++) {
        if (k < 6) asm volatile("cp.async.wait_group 1;" ::: "memory");
        else       asm volatile("cp.async.wait_group 0;" ::: "memory");
        __syncwarp();

        const float4* rp = reinterpret_cast<const float4*>(wring + (k & 1) * 1024);
        float s1 = 0.f, s2 = 0.f;
#pragma unroll
        for (int j = 0; j < 8; j++) {
            float4 x = rp[l + 32 * j];
            colacc[j].x += x.x; colacc[j].y += x.y; colacc[j].z += x.z; colacc[j].w += x.w;
            s1 += (x.x + x.y) + (x.z + x.w);
            s2 += (x.x * x.x + x.y * x.y) + (x.z * x.z + x.w * x.w);
        }
        double d1 = (double)s1, d2 = (double)s2;
#pragma unroll
        for (int off = 16; off; off >>= 1) {
            d1 += __shfl_down_sync(0xffffffffu, d1, off);
            d2 += __shfl_down_sync(0xffffffffu, d2, off);
        }
        if (l == 0) {
            double var = (d2 - d1 * d1 * (1.0 / (double)D)) * (1.0 / (double)(D - 1));
            float e = (float)sqrt(var > 0.0 ? var : 0.0);
            const int s = row0 + k;
            if (esel == 0) g_entropy[(size_t)n * S + s] = e;
            else           g_entropy2[s] = e;
        }
        __syncwarp();
        if (k < 6) issue_row(rowbase + (size_t)(k + 2) * D, wring + (k & 1) * 1024, l);
    }

    // deterministic column-sum combine across the 8 warps
#pragma unroll
    for (int j = 0; j < 8; j++)
        reinterpret_cast<float4*>(&cs[w * 1024 + 4 * (l + 32 * j)])[0] = colacc[j];
    __syncthreads();
#pragma unroll
    for (int g = 0; g < 4; g++) {
        const int d = t + 256 * g;
        float ssum = 0.f;
#pragma unroll
        for (int w2 = 0; w2 < 8; w2++) ssum += cs[w2 * 1024 + d];
        g_part[(size_t)(part_base + bx) * D + d] = ssum;
    }
}

// ---------------- kernel B: reduce partial colsums -> colmean (33 blocks) ----------
__global__ void colmean_kernel()
{
    const int n = blockIdx.x, t = threadIdx.x;
#pragma unroll
    for (int g = 0; g < 4; g++) {
        const int d = t + 256 * g;
        float s = 0.f;
#pragma unroll 8
        for (int p = 0; p < TILES; p++) s += g_part[(size_t)(n * TILES + p) * D + d];
        g_colmean[n * D + d] = s * (1.0f / (float)S);
    }
}

// ---------------- kernel C: top-32 of 2048 entropies (256 threads, reg-resident) ----
// key = (float_bits << 32) | ~idx : u64 max == (value desc, then lowest index)
__global__ void __launch_bounds__(256) topk_kernel(int esel, int osel)
{
    const int n = blockIdx.x;
    const int t = threadIdx.x;
    const int w = t >> 5, l = t & 31;
    const float* e = (esel == 0) ? (g_entropy + (size_t)n * S) : g_entropy2;

    unsigned long long key[8];
#pragma unroll
    for (int j = 0; j < 8; j++) {
        const int idx = t + 256 * j;
        const unsigned v = __float_as_uint(e[idx]);       // entropy >= 0 -> uint order ok
        key[j] = ((unsigned long long)v << 32) | (unsigned)(~idx);
    }

    __shared__ unsigned long long warpbest[8];
    __shared__ unsigned long long win_s;

    for (int it = 0; it < PATCH; it++) {
        unsigned long long b = key[0];
#pragma unroll
        for (int j = 1; j < 8; j++) b = (key[j] > b) ? key[j] : b;
#pragma unroll
        for (int off = 16; off; off >>= 1) {
            unsigned long long o = __shfl_down_sync(0xffffffffu, b, off);
            b = (o > b) ? o : b;
        }
        if (l == 0) warpbest[w] = b;
        __syncthreads();
        if (t == 0) {
            unsigned long long bb = warpbest[0];
#pragma unroll
            for (int j = 1; j < 8; j++) bb = (warpbest[j] > bb) ? warpbest[j] : bb;
            win_s = bb;
            const int idx = (int)(~(unsigned)(bb & 0xffffffffu));
            if (osel == 0) g_topidx[n * PATCH + it] = idx;
            else           g_fidx[it] = idx;
        }
        __syncthreads();
        const unsigned long long win = win_s;
#pragma unroll
        for (int j = 0; j < 8; j++) if (key[j] == win) key[j] = 0ull;
    }
}

// ---------------- kernel D: agg = query copy, out[0..S*D) = 0 -----------------------
__global__ void init_agg_kernel(const float* __restrict__ q, float* __restrict__ out)
{
    const int i = blockIdx.x * blockDim.x + threadIdx.x;  // float4 index
    float4 v = reinterpret_cast<const float4*>(q)[i];
    reinterpret_cast<float4*>(g_agg)[i] = v;
    reinterpret_cast<float4*>(out)[i] = make_float4(0.f, 0.f, 0.f, 0.f);
}

__device__ __forceinline__ float trunc_clip(float x)
{
    return truncf(fminf(fmaxf(x, -128.f), 127.f));
}

// ---------------- kernel E: scatter truncated patches into agg ----------------------
__global__ void scatter_kernel(const float* __restrict__ mem)
{
    const int b = blockIdx.x;
    const int n = b >> 5, j = b & 31;
    const int row = g_topidx[n * PATCH + j];
    const int t = threadIdx.x;
    float4 x = reinterpret_cast<const float4*>(mem + ((size_t)n * S + row) * D)[t];
    float* dst = g_agg + (size_t)row * D + 4 * t;
    atomicAdd(dst + 0, trunc_clip(x.x));
    atomicAdd(dst + 1, trunc_clip(x.y));
    atomicAdd(dst + 2, trunc_clip(x.z));
    atomicAdd(dst + 3, trunc_clip(x.w));
}

// ---------------- kernel H: write recon rows -----------------------------------------
__global__ void recon_kernel(float* __restrict__ out)
{
    const int row = g_fidx[blockIdx.x];
    const int t = threadIdx.x;
    float4 x = reinterpret_cast<float4*>(g_agg + (size_t)row * D)[t];
    const float inv = 1.0f / 33.0f;
    float4 r;
    r.x = trunc_clip(x.x * inv);
    r.y = trunc_clip(x.y * inv);
    r.z = trunc_clip(x.z * inv);
    r.w = trunc_clip(x.w * inv);
    reinterpret_cast<float4*>(out + (size_t)row * D)[t] = r;
}

// ---------------- kernel M: meta MLP (33 blocks x 128 threads) -----------------------
__global__ void mlp_kernel(const float* __restrict__ surprise,
                           const float* __restrict__ W1, const float* __restrict__ b1,
                           const float* __restrict__ W2, const float* __restrict__ b2)
{
    const int n = blockIdx.x;       // 0..31 memories, 32 = query
    const int t = threadIdx.x;      // 128
    __shared__ float feat[1028];
    __shared__ float hsm[128];
    __shared__ double red[128];

#pragma unroll
    for (int g = 0; g < 8; g++) feat[t + 128 * g] = g_colmean[n * D + t + 128 * g];
    if (t == 0) {
        feat[1024] = (n < NMEM) ? surprise[n] : 0.f;
        feat[1025] = 0.f; feat[1026] = 0.f;
    }
    __syncthreads();

    // layer 1: 4 independent accumulators to break the FMA chain
    float a0 = b1[t], a1 = 0.f, a2 = 0.f, a3 = 0.f;
    for (int i = 0; i < 1024; i += 4) {
        a0 = fmaf(feat[i + 0], W1[(i + 0) * 128 + t], a0);
        a1 = fmaf(feat[i + 1], W1[(i + 1) * 128 + t], a1);
        a2 = fmaf(feat[i + 2], W1[(i + 2) * 128 + t], a2);
        a3 = fmaf(feat[i + 3], W1[(i + 3) * 128 + t], a3);
    }
    for (int i = 1024; i < 1027; i++) a0 = fmaf(feat[i], W1[i * 128 + t], a0);
    float acc = (a0 + a1) + (a2 + a3);
    hsm[t] = acc > 0.f ? acc : 0.f;
    __syncthreads();

    double nrm = 0.0;
#pragma unroll
    for (int g = 0; g < 8; g++) {
        const int d = t + 128 * g;
        float e = b2[d];
#pragma unroll 8
        for (int k = 0; k < 128; k++) e = fmaf(hsm[k], W2[k * D + d], e);
        g_emb[n * D + d] = e;
        nrm += (double)e * (double)e;
    }
    red[t] = nrm;
    __syncthreads();
#pragma unroll
    for (int off = 64; off; off >>= 1) { if (t < off) red[t] += red[t + off]; __syncthreads(); }
    if (t == 0) g_norm[n] = sqrt(red[0]);
}

// ---------------- kernel S: parallel cosine sims (32 blocks x 256 threads) ----------
__global__ void sims_kernel(const float* __restrict__ pm, float* __restrict__ out)
{
    const int n = blockIdx.x, t = threadIdx.x;
    double p = 0.0;
#pragma unroll
    for (int g = 0; g < 4; g++) {
        const int d = t + 256 * g;
        p += (double)g_emb[n * D + d] * (double)g_emb[NMEM * D + d];
    }
    __shared__ double red[256];
    red[t] = p;
    __syncthreads();
#pragma unroll
    for (int off = 128; off; off >>= 1) { if (t < off) red[t] += red[t + off]; __syncthreads(); }
    if (t == 0) {
        double sim = red[0] / (fmax(g_norm[n], 1e-8) * fmax(g_norm[NMEM], 1e-8)) * (double)pm[n];
        out[(size_t)S * D + n] = (float)sim;
    }
}

// ---------------- kernel T: descending argsort of 32 sims (ties -> lower idx) -------
__global__ void argsort_kernel(float* __restrict__ out)
{
    if (threadIdx.x != 0) return;
    float ss[NMEM];
    for (int i = 0; i < NMEM; i++) ss[i] = out[(size_t)S * D + i];
    bool used[NMEM];
    for (int i = 0; i < NMEM; i++) used[i] = false;
    for (int r = 0; r < NMEM; r++) {
        float bv = -FLT_MAX; int bi = 0;
        for (int i = 0; i < NMEM; i++)
            if (!used[i] && ss[i] > bv) { bv = ss[i]; bi = i; }
        used[bi] = true;
        out[(size_t)S * D + NMEM + r] = (float)bi;
    }
}

// ---------------- launch ------------------------------------------------------------
extern "C" void kernel_launch(void* const* d_in, const int* in_sizes, int n_in,
                              void* d_out, int out_size)
{
    const float* query    = (const float*)d_in[0];
    const float* memories = (const float*)d_in[1];
    const float* surprise = (const float*)d_in[2];
    const float* pm       = (const float*)d_in[3];
    const float* W1       = (const float*)d_in[4];
    const float* b1       = (const float*)d_in[5];
    const float* W2       = (const float*)d_in[6];
    const float* b2       = (const float*)d_in[7];
    float* out = (float*)d_out;

    const int ROWSTATS_SMEM = 96 * 1024;
    cudaFuncSetAttribute(rowstats_kernel,
                         cudaFuncAttributeMaxDynamicSharedMemorySize, ROWSTATS_SMEM);

    // 1) per-memory row entropy + partial colsums (the one big 268MB pass)
    rowstats_kernel<<<NMEM * TILES, 256, ROWSTATS_SMEM>>>(memories, 0, 0);
    // 2) query colsums
    rowstats_kernel<<<TILES, 256, ROWSTATS_SMEM>>>(query, 1, NMEM * TILES);
    // 3) colmeans
    colmean_kernel<<<NMEM + 1, 256>>>();
    // 4) per-memory top-32 entropy rows
    topk_kernel<<<NMEM, 256>>>(0, 0);
    // 5) agg = query, zero recon region of out
    init_agg_kernel<<<(S * D / 4) / 256, 256>>>(query, out);
    // 6) scatter truncated patches (exact integer fp adds)
    scatter_kernel<<<NMEM * PATCH, 256>>>(memories);
    // 7) row entropy of aggregated
    rowstats_kernel<<<TILES, 256, ROWSTATS_SMEM>>>(nullptr, 1, (NMEM + 1) * TILES);
    // 8) final top-32 rows
    topk_kernel<<<1, 256>>>(1, 1);
    // 9) recon rows
    recon_kernel<<<PATCH, 256>>>(out);
    // 10) meta-learner embeddings + norms
    mlp_kernel<<<NMEM + 1, 128>>>(surprise, W1, b1, W2, b2);
    // 11) sims
    sims_kernel<<<NMEM, 256>>>(pm, out);
    // 12) top_idx
    argsort_kernel<<<1, 32>>>(out);
}